// round 11
// baseline (speedup 1.0000x reference)
#include <cuda_runtime.h>
#include <cuda_bf16.h>
#include <math.h>
#include <cstdint>

#define BB 256
#define SS 4096
#define HH 64
#define GG 192   // 3*H
#define RB 8     // batches per rec CTA

// Scratch
__device__ float g_buf[(size_t)BB * SS * HH];      // 268 MB  layer activations
__device__ float g_xi [(size_t)BB * SS * GG];      // 805 MB  xi incl. b_ih, layout [b][t][row]
__device__ float g_scores[(size_t)BB * 4 * SS];    // 16 MB

__device__ __forceinline__ float sigmoidf_(float x) {
    return 1.0f / (1.0f + __expf(-x));
}
__device__ __forceinline__ float tanhf_(float x) {
    x = fminf(fmaxf(x, -15.0f), 15.0f);
    float e = __expf(2.0f * x);
    return (e - 1.0f) / (e + 1.0f);
}

// ---- tf32 helpers (xi gemm, verified R7) ----
__device__ __forceinline__ uint32_t f2tf32_(float x) {
    uint32_t r;
    asm("cvt.rna.tf32.f32 %0, %1;" : "=r"(r) : "f"(x));
    return r;
}
__device__ __forceinline__ void mma_tf32_(float* c, const uint32_t* a, const uint32_t* b) {
    asm volatile("mma.sync.aligned.m16n8k8.row.col.f32.tf32.tf32.f32 "
        "{%0,%1,%2,%3},{%4,%5,%6,%7},{%8,%9},{%0,%1,%2,%3};"
        : "+f"(c[0]), "+f"(c[1]), "+f"(c[2]), "+f"(c[3])
        : "r"(a[0]), "r"(a[1]), "r"(a[2]), "r"(a[3]), "r"(b[0]), "r"(b[1]));
}

// ---- bf16 m16n8k16 mma (recurrence, verified R10) ----
__device__ __forceinline__ void mma_bf16_(float* c, const uint32_t* a, const uint32_t* b) {
    asm volatile("mma.sync.aligned.m16n8k16.row.col.f32.bf16.bf16.f32 "
        "{%0,%1,%2,%3},{%4,%5,%6,%7},{%8,%9},{%0,%1,%2,%3};"
        : "+f"(c[0]), "+f"(c[1]), "+f"(c[2]), "+f"(c[3])
        : "r"(a[0]), "r"(a[1]), "r"(a[2]), "r"(a[3]), "r"(b[0]), "r"(b[1]));
}
__device__ __forceinline__ uint32_t packbf2_(float v0, float v1) {
    __nv_bfloat16 a = __float2bfloat16(v0), b = __float2bfloat16(v1);
    return (uint32_t)__bfloat16_as_ushort(a) | ((uint32_t)__bfloat16_as_ushort(b) << 16);
}

// ---------------------------------------------------------------------------
// xi0: g_xi[b][t][row] = wih0[row]*x[b][t] + bih0[row]
// ---------------------------------------------------------------------------
__global__ __launch_bounds__(GG)
void xi0_kernel(const float* __restrict__ x,
                const float* __restrict__ wih0, const float* __restrict__ bih0)
{
    __shared__ float xs[16];
    const int j = threadIdx.x;
    const int t0 = blockIdx.x * 16;
    const int b = blockIdx.y;
    if (j < 16) xs[j] = x[(size_t)b * SS + t0 + j];
    const float w = wih0[j], bi = bih0[j];
    __syncthreads();
    float* outp = g_xi + ((size_t)b * SS + t0) * GG + j;
#pragma unroll
    for (int tt = 0; tt < 16; tt++)
        outp[(size_t)tt * GG] = fmaf(w, xs[tt], bi);
}

// ---------------------------------------------------------------------------
// r/z/n-stacked mma recurrence. One CTA = 8 batches, 128 threads (4 warps).
// Warp w owns rows [16w,16w+16) of EACH gate matrix (r = whh[0:64],
// z = whh[64:128], n = whh[128:192]); per step 3 C-matrices [64x8] via
// 3-term bf16 hi/lo mma (verified numerics). Every thread then holds
// r,z,n for its own (k,batch) cells -> gates + h-update fully thread-local,
// ONE __syncthreads per step. h kept packed bf16 hi/lo in double-buffered
// smem (16-bit STS, no shuffles). xi staged in a 4-deep smem ring.
// ---------------------------------------------------------------------------
__global__ __launch_bounds__(128)
void rec8_kernel(const float* __restrict__ whh, const float* __restrict__ bhh)
{
    __shared__ uint32_t shh[2][32][8], shl[2][32][8];  // packed h pairs [buf][k/2][b]
    __shared__ float sxi[4][RB][196];                  // 4-deep ring, conflict-free pad

    const int tid = threadIdx.x;
    const int wid = tid >> 5, lane = tid & 31;
    const int g = lane >> 2, q = lane & 3;
    const int k0 = wid * 16 + g, k1 = k0 + 8;
    const int b0c = blockIdx.x * RB;

    // ---- weight fragments: 3 gates x 4 k-chunks x 4 elems, bf16 hi/lo ----
    uint32_t wf[3][2][4][4];   // [gate][hi/lo][kt][e]
#pragma unroll
    for (int gate = 0; gate < 3; gate++) {
#pragma unroll
        for (int kt = 0; kt < 4; kt++) {
#pragma unroll
            for (int e = 0; e < 4; e++) {
                int rr = gate * HH + wid * 16 + g + (e & 1) * 8;
                int cc = kt * 16 + 2 * q + (e >> 1) * 8;
                float v0 = whh[rr * HH + cc], v1 = whh[rr * HH + cc + 1];
                __nv_bfloat16 h0 = __float2bfloat16(v0), h1 = __float2bfloat16(v1);
                wf[gate][0][kt][e] = (uint32_t)__bfloat16_as_ushort(h0) |
                                     ((uint32_t)__bfloat16_as_ushort(h1) << 16);
                wf[gate][1][kt][e] = packbf2_(v0 - __bfloat162float(h0),
                                              v1 - __bfloat162float(h1));
            }
        }
    }
    const float bhr0 = bhh[k0],        bhr1 = bhh[k1];
    const float bhz0 = bhh[HH + k0],   bhz1 = bhh[HH + k1];
    const float bhn0 = bhh[128 + k0],  bhn1 = bhh[128 + k1];

    // zero both h buffers (2*256 + 2*256 u32 = 1024 words)
#pragma unroll
    for (int i = 0; i < 4; i++) {
        ((uint32_t*)shh)[tid + i * 128] = 0u;
        ((uint32_t*)shl)[tid + i * 128] = 0u;
    }

    // initial xi fill: slots 0,1 (t = 0,1). 8 batches x 192 floats each.
#pragma unroll
    for (int r = 0; r < 3; r++) {
        int idx = tid + r * 128;           // 0..383
        int bb = idx / 48, f4 = (idx % 48) * 4;
        const float* src = g_xi + ((size_t)(b0c + bb) * SS) * GG + f4;
        *(float4*)&sxi[0][bb][f4] = *(const float4*)src;
        *(float4*)&sxi[1][bb][f4] = *(const float4*)(src + GG);
    }
    __syncthreads();

    float hold[4] = {0.f, 0.f, 0.f, 0.f};   // cells (k0,b0)(k0,b1)(k1,b0)(k1,b1)
    const int pb = tid / 48, pf4 = (tid % 48) * 4;          // prefetch duty (tid<... covers via 3 iters)
    int p = 0;

    for (int t = 0; t < SS; t++) {
        const int s = t & 3;

        // ---- B fragments from packed h (conflict-free: addr = kp*8+g) ----
        uint32_t bh[4][2], bl[4][2];
#pragma unroll
        for (int kt = 0; kt < 4; kt++) {
            bh[kt][0] = shh[p][kt * 8 + q][g];
            bh[kt][1] = shh[p][kt * 8 + q + 4][g];
            bl[kt][0] = shl[p][kt * 8 + q][g];
            bl[kt][1] = shl[p][kt * 8 + q + 4][g];
        }

        // ---- xi for my 12 cells ----
        const int bA = 2 * q, bB = 2 * q + 1;
        const float xr00 = sxi[s][bA][k0],        xr01 = sxi[s][bB][k0];
        const float xr10 = sxi[s][bA][k1],        xr11 = sxi[s][bB][k1];
        const float xz00 = sxi[s][bA][HH + k0],   xz01 = sxi[s][bB][HH + k0];
        const float xz10 = sxi[s][bA][HH + k1],   xz11 = sxi[s][bB][HH + k1];
        const float xn00 = sxi[s][bA][128 + k0],  xn01 = sxi[s][bB][128 + k0];
        const float xn10 = sxi[s][bA][128 + k1],  xn11 = sxi[s][bB][128 + k1];

        // ---- prefetch xi[t+2] (slot (t+2)&3; safe: last read 2 bars ago) ----
        float4 pf[3];
#pragma unroll
        for (int r = 0; r < 3; r++) {
            int idx = tid + r * 128;
            int bb = idx / 48, f4 = (idx % 48) * 4;
            pf[r] = (t + 2 < SS)
                ? *(const float4*)(g_xi + ((size_t)(b0c + bb) * SS + (t + 2)) * GG + f4)
                : make_float4(0.f, 0.f, 0.f, 0.f);
        }

        // ---- 36 HMMA: 3 gates x (hi*hi + lo*hi + hi*lo) x 4 kt, interleaved ----
        float cr[4] = {0,0,0,0}, cz[4] = {0,0,0,0}, cn[4] = {0,0,0,0};
#pragma unroll
        for (int kt = 0; kt < 4; kt++) {
            mma_bf16_(cr, wf[0][0][kt], bh[kt]);
            mma_bf16_(cz, wf[1][0][kt], bh[kt]);
            mma_bf16_(cn, wf[2][0][kt], bh[kt]);
        }
#pragma unroll
        for (int kt = 0; kt < 4; kt++) {
            mma_bf16_(cr, wf[0][1][kt], bh[kt]);
            mma_bf16_(cz, wf[1][1][kt], bh[kt]);
            mma_bf16_(cn, wf[2][1][kt], bh[kt]);
        }
#pragma unroll
        for (int kt = 0; kt < 4; kt++) {
            mma_bf16_(cr, wf[0][0][kt], bl[kt]);
            mma_bf16_(cz, wf[1][0][kt], bl[kt]);
            mma_bf16_(cn, wf[2][0][kt], bl[kt]);
        }

        // ---- gates + h update, fully thread-local ----
        const float xrv[4] = {xr00, xr01, xr10, xr11};
        const float xzv[4] = {xz00, xz01, xz10, xz11};
        const float xnv[4] = {xn00, xn01, xn10, xn11};
        const float bhrv[4] = {bhr0, bhr0, bhr1, bhr1};
        const float bhzv[4] = {bhz0, bhz0, bhz1, bhz1};
        const float bhnv[4] = {bhn0, bhn0, bhn1, bhn1};
        const int kcell[4] = {k0, k0, k1, k1};
        const int bcell[4] = {bA, bB, bA, bB};

#pragma unroll
        for (int c = 0; c < 4; c++) {
            const float rv = sigmoidf_(cr[c] + bhrv[c] + xrv[c]);
            const float zv = sigmoidf_(cz[c] + bhzv[c] + xzv[c]);
            const float nv = tanhf_(fmaf(rv, cn[c] + bhnv[c], xnv[c]));
            const float hn = fmaf(zv, hold[c] - nv, nv);
            hold[c] = hn;

            g_buf[((size_t)(b0c + bcell[c]) * SS + t) * HH + kcell[c]] = hn;

            // bf16 hi/lo -> 16-bit stores into the OTHER h buffer
            __nv_bfloat16 hb = __float2bfloat16(hn);
            __nv_bfloat16 lb = __float2bfloat16(hn - __bfloat162float(hb));
            uint16_t* ph = (uint16_t*)&shh[1 - p][kcell[c] >> 1][bcell[c]];
            uint16_t* pl = (uint16_t*)&shl[1 - p][kcell[c] >> 1][bcell[c]];
            ph[kcell[c] & 1] = __bfloat16_as_ushort(hb);
            pl[kcell[c] & 1] = __bfloat16_as_ushort(lb);
        }

        // ---- store prefetched xi ----
        if (t + 2 < SS) {
            const int sd = (t + 2) & 3;
#pragma unroll
            for (int r = 0; r < 3; r++) {
                int idx = tid + r * 128;
                int bb = idx / 48, f4 = (idx % 48) * 4;
                *(float4*)&sxi[sd][bb][f4] = pf[r];
            }
        }

        __syncthreads();
        p ^= 1;
    }
    (void)pb; (void)pf4;
}

// ---------------------------------------------------------------------------
// xi GEMM on mma.sync tf32 (hi/lo, fp32 accum) — verified R7 (679us).
// ---------------------------------------------------------------------------
__global__ __launch_bounds__(512, 1)
void xi_gemm_mma(const float* __restrict__ wih, const float* __restrict__ bih)
{
    __shared__ __align__(16) float sA[128 * 68];

    const int tid = threadIdx.x;
    const int wid = tid >> 5, lane = tid & 31;
    const int wm = wid & 3, wn = wid >> 2;
    const int g = lane >> 2, q = lane & 3;
    const size_t row0 = (size_t)blockIdx.x * 128;

    {
        const float4* src = (const float4*)(g_buf + row0 * HH);
#pragma unroll
        for (int i = 0; i < 4; i++) {
            int idx = tid + i * 512;
            int rr = idx >> 4, c4 = idx & 15;
            float4 v = src[idx];
            *(float4*)(sA + rr * 68 + c4 * 4) = v;
        }
    }
    __syncthreads();

    float c[2][6][4] = {};

    for (int kt = 0; kt < 8; kt++) {
        uint32_t ah[2][4], al[2][4];
#pragma unroll
        for (int mt = 0; mt < 2; mt++) {
#pragma unroll
            for (int e = 0; e < 4; e++) {
                int row = wm * 32 + mt * 16 + g + (e & 1) * 8;
                int col = kt * 8 + q + (e >> 1) * 4;
                float v = sA[row * 68 + col];
                uint32_t hi = f2tf32_(v);
                ah[mt][e] = hi;
                al[mt][e] = f2tf32_(v - __uint_as_float(hi));
            }
        }
        uint32_t bh[6][2], bl[6][2];
#pragma unroll
        for (int nt = 0; nt < 6; nt++) {
#pragma unroll
            for (int e = 0; e < 2; e++) {
                int n = wn * 48 + nt * 8 + g;
                int k = kt * 8 + q + e * 4;
                float v = __ldg(&wih[n * 64 + k]);
                uint32_t hi = f2tf32_(v);
                bh[nt][e] = hi;
                bl[nt][e] = f2tf32_(v - __uint_as_float(hi));
            }
        }
#pragma unroll
        for (int mt = 0; mt < 2; mt++) {
#pragma unroll
            for (int nt = 0; nt < 6; nt++) {
                mma_tf32_(c[mt][nt], ah[mt], bh[nt]);
                mma_tf32_(c[mt][nt], al[mt], bh[nt]);
                mma_tf32_(c[mt][nt], ah[mt], bl[nt]);
            }
        }
    }

#pragma unroll
    for (int mt = 0; mt < 2; mt++) {
        const size_t row = row0 + wm * 32 + mt * 16 + g;
#pragma unroll
        for (int nt = 0; nt < 6; nt++) {
            const int col = wn * 48 + nt * 8 + q * 2;
            const float b0v = __ldg(&bih[col]);
            const float b1v = __ldg(&bih[col + 1]);
            *(float2*)(g_xi + row * GG + col) =
                make_float2(c[mt][nt][0] + b0v, c[mt][nt][1] + b1v);
            *(float2*)(g_xi + (row + 8) * GG + col) =
                make_float2(c[mt][nt][2] + b0v, c[mt][nt][3] + b1v);
        }
    }
}

// ---------------------------------------------------------------------------
// Attention + head (unchanged; known-good).
// ---------------------------------------------------------------------------
__global__ __launch_bounds__(256)
void attn_kernel(
    const float* __restrict__ in_proj_w, const float* __restrict__ in_proj_b,
    const float* __restrict__ out_proj_w, const float* __restrict__ out_proj_b,
    const float* __restrict__ fc_w, const float* __restrict__ fc_b,
    float* __restrict__ out)
{
    const int b = blockIdx.x;
    const int tid = threadIdx.x;

    __shared__ __align__(16) float shl2[HH];
    __shared__ __align__(16) float sq[HH];
    __shared__ __align__(16) float sg[4][HH];
    __shared__ float sc[4];
    __shared__ float sred[4][256];
    __shared__ float sm4[4], sl4[4];
    __shared__ __align__(16) float stile[64][HH];
    __shared__ float sw[4][64];
    __shared__ float su[4][HH];
    __shared__ __align__(16) float sctx[HH];
    __shared__ float sao[HH];

    const float* mybuf = g_buf + (size_t)b * SS * HH;

    if (tid < HH) shl2[tid] = mybuf[(size_t)(SS - 1) * HH + tid];
    __syncthreads();

    if (tid < HH) {
        float acc = in_proj_b[tid];
#pragma unroll
        for (int k = 0; k < HH; k++)
            acc = fmaf(in_proj_w[tid * HH + k], shl2[k], acc);
        sq[tid] = acc;
    }
    __syncthreads();

    if (tid < HH) {
#pragma unroll
        for (int h = 0; h < 4; h++) {
            float acc = 0.0f;
#pragma unroll
            for (int d = 0; d < 16; d++)
                acc = fmaf(sq[h * 16 + d], in_proj_w[(HH + h * 16 + d) * HH + tid], acc);
            sg[h][tid] = acc * 0.25f;
        }
    }
    if (tid < 4) {
        float acc = 0.0f;
#pragma unroll
        for (int d = 0; d < 16; d++)
            acc = fmaf(sq[tid * 16 + d], in_proj_b[HH + tid * 16 + d], acc);
        sc[tid] = acc * 0.25f;
    }
    __syncthreads();

    float mloc[4] = {-1e30f, -1e30f, -1e30f, -1e30f};
    for (int s = tid; s < SS; s += 256) {
        const float4* ov = (const float4*)(mybuf + (size_t)s * HH);
        float4 o[16];
#pragma unroll
        for (int kk = 0; kk < 16; kk++) o[kk] = ov[kk];
#pragma unroll
        for (int h = 0; h < 4; h++) {
            const float4* gv = (const float4*)sg[h];
            float a0 = sc[h], a1 = 0.f, a2 = 0.f, a3 = 0.f;
#pragma unroll
            for (int kk = 0; kk < 16; kk++) {
                float4 g4 = gv[kk];
                a0 = fmaf(g4.x, o[kk].x, a0);
                a1 = fmaf(g4.y, o[kk].y, a1);
                a2 = fmaf(g4.z, o[kk].z, a2);
                a3 = fmaf(g4.w, o[kk].w, a3);
            }
            float sv = (a0 + a1) + (a2 + a3);
            g_scores[((size_t)(b * 4 + h)) * SS + s] = sv;
            mloc[h] = fmaxf(mloc[h], sv);
        }
    }
#pragma unroll
    for (int h = 0; h < 4; h++) sred[h][tid] = mloc[h];
    __syncthreads();
    if (tid < 4) {
        float m = -1e30f;
        for (int i = 0; i < 256; i++) m = fmaxf(m, sred[tid][i]);
        sm4[tid] = m;
    }
    __syncthreads();

    const int h = tid >> 6;
    const int e = tid & 63;
    const float mh = sm4[h];
    float uacc = 0.0f, lloc = 0.0f;

    for (int tile = 0; tile < SS / 64; tile++) {
        const int s0 = tile * 64;
        {
            float4* st4 = (float4*)stile;
            const float4* gv = (const float4*)(mybuf + (size_t)s0 * HH);
#pragma unroll
            for (int r = 0; r < 4; r++) {
                int idx = tid + r * 256;
                st4[idx] = gv[idx];
            }
        }
        {
            float w = __expf(g_scores[((size_t)(b * 4 + h)) * SS + s0 + e] - mh);
            sw[h][e] = w;
            lloc += w;
        }
        __syncthreads();
#pragma unroll
        for (int sp = 0; sp < 64; sp++)
            uacc = fmaf(sw[h][sp], stile[sp][e], uacc);
        __syncthreads();
    }

    ((float*)sred)[tid] = lloc;
    __syncthreads();
    if (tid < 4) {
        float l = 0.0f;
        for (int i = 0; i < 64; i++) l += ((float*)sred)[tid * 64 + i];
        sl4[tid] = l;
    }
    __syncthreads();

    su[h][e] = uacc / sl4[h];
    __syncthreads();

    if (tid < HH) {
        const int hh = tid >> 4;
        float acc = in_proj_b[128 + tid];
#pragma unroll
        for (int k = 0; k < HH; k++)
            acc = fmaf(in_proj_w[(128 + tid) * HH + k], su[hh][k], acc);
        sctx[tid] = acc;
    }
    __syncthreads();

    if (tid < HH) {
        float acc = out_proj_b[tid];
#pragma unroll
        for (int k = 0; k < HH; k++)
            acc = fmaf(out_proj_w[tid * HH + k], sctx[k], acc);
        sao[tid] = fc_w[tid] * acc;
    }
    __syncthreads();

    if (tid == 0) {
        float lg = fc_b[0];
        for (int i = 0; i < HH; i++) lg += sao[i];
        out[b] = 1.0f / (1.0f + __expf(-lg));
    }
}

// ---------------------------------------------------------------------------
extern "C" void kernel_launch(void* const* d_in, const int* in_sizes, int n_in,
                              void* d_out, int out_size)
{
    const float* x    = (const float*)d_in[0];
    const float* wih0 = (const float*)d_in[1];
    const float* whh0 = (const float*)d_in[2];
    const float* bih0 = (const float*)d_in[3];
    const float* bhh0 = (const float*)d_in[4];
    const float* wih1 = (const float*)d_in[5];
    const float* whh1 = (const float*)d_in[6];
    const float* bih1 = (const float*)d_in[7];
    const float* bhh1 = (const float*)d_in[8];
    const float* wih2 = (const float*)d_in[9];
    const float* whh2 = (const float*)d_in[10];
    const float* bih2 = (const float*)d_in[11];
    const float* bhh2 = (const float*)d_in[12];
    const float* ipw  = (const float*)d_in[13];
    const float* ipb  = (const float*)d_in[14];
    const float* opw  = (const float*)d_in[15];
    const float* opb  = (const float*)d_in[16];
    const float* fcw  = (const float*)d_in[17];
    const float* fcb  = (const float*)d_in[18];

    xi0_kernel<<<dim3(SS / 16, BB), GG>>>(x, wih0, bih0);   // #1
    rec8_kernel<<<BB / RB, 128>>>(whh0, bhh0);              // #2  layer 0
    xi_gemm_mma<<<8192, 512>>>(wih1, bih1);                 // #3
    rec8_kernel<<<BB / RB, 128>>>(whh1, bhh1);              // #4  layer 1
    xi_gemm_mma<<<8192, 512>>>(wih2, bih2);                 // #5
    rec8_kernel<<<BB / RB, 128>>>(whh2, bhh2);              // #6  layer 2
    attn_kernel<<<BB, 256>>>(ipw, ipb, opw, opb, fcw, fcb, (float*)d_out);
}

// round 12
// speedup vs baseline: 1.8645x; 1.8645x over previous
#include <cuda_runtime.h>
#include <math.h>

#define BB 256
#define SS 4096
#define HH 64
#define GG 192   // 3*H

// Scratch
__device__ float g_buf[(size_t)BB * SS * HH];      // 268 MB  layer activations
__device__ float g_scores[(size_t)BB * 4 * SS];    // 16 MB

__device__ __forceinline__ float sigmoidf_(float x) {
    return 1.0f / (1.0f + __expf(-x));
}
__device__ __forceinline__ float tanhf_(float x) {
    x = fminf(fmaxf(x, -15.0f), 15.0f);
    float e = __expf(2.0f * x);
    return (e - 1.0f) / (e + 1.0f);
}

// dot of 64-reg weight row with smem vector (float4 broadcast reads), R1-proven
__device__ __forceinline__ float dot64_(const float* __restrict__ w, const float* sv) {
    const float4* hv = (const float4*)sv;
    float a0 = 0.f, a1 = 0.f, a2 = 0.f, a3 = 0.f;
#pragma unroll
    for (int kk = 0; kk < 16; kk++) {
        float4 v = hv[kk];
        a0 = fmaf(w[4 * kk + 0], v.x, a0);
        a1 = fmaf(w[4 * kk + 1], v.y, a1);
        a2 = fmaf(w[4 * kk + 2], v.z, a2);
        a3 = fmaf(w[4 * kk + 3], v.w, a3);
    }
    return (a0 + a1) + (a2 + a3);
}

// ---------------------------------------------------------------------------
// Layer 0: one CTA = TWO batches, 192 threads = one gate row each, plain fp32.
// wh (64 regs) shared across both batches; two independent h-dots give ILP.
// grid = 128 -> one wave. x is scalar/step: 4-deep broadcast-LDG rings.
// ---------------------------------------------------------------------------
__global__ __launch_bounds__(GG, 1)
void rec0_kernel(const float* __restrict__ x,
                 const float* __restrict__ wih, const float* __restrict__ whh,
                 const float* __restrict__ bih, const float* __restrict__ bhh)
{
    __shared__ __align__(16) float sh[2][HH];
    __shared__ float srz[2][128];

    const int j = threadIdx.x;
    const int b0 = 2 * blockIdx.x, b1 = b0 + 1;
    const float* xin0 = x + (size_t)b0 * SS;
    const float* xin1 = x + (size_t)b1 * SS;
    float* out0 = g_buf + (size_t)b0 * SS * HH;
    float* out1 = g_buf + (size_t)b1 * SS * HH;

    float wh[HH];
#pragma unroll
    for (int k = 0; k < HH; k++) wh[k] = whh[j * HH + k];
    const float wi = wih[j];
    const float bi = bih[j];
    const float bh = bhh[j];

    float xr0[4], xr1[4];
#pragma unroll
    for (int i = 0; i < 4; i++) { xr0[i] = xin0[i]; xr1[i] = xin1[i]; }

    if (j < HH) { sh[0][j] = 0.0f; sh[1][j] = 0.0f; }
    __syncthreads();

    for (int t = 0; t < SS; t++) {
        const float ai0 = fmaf(wi, xr0[t & 3], bi);
        const float ai1 = fmaf(wi, xr1[t & 3], bi);
        const float ah0 = dot64_(wh, sh[0]) + bh;
        const float ah1 = dot64_(wh, sh[1]) + bh;
        const int tp = t + 4;
        if (tp < SS) { xr0[t & 3] = xin0[tp]; xr1[t & 3] = xin1[tp]; }
        if (j < 128) {
            srz[0][j] = sigmoidf_(ai0 + ah0);
            srz[1][j] = sigmoidf_(ai1 + ah1);
        }
        __syncthreads();
        if (j >= 128) {
            const int k = j - 128;
            {
                float r = srz[0][k], z = srz[0][64 + k];
                float n = tanhf_(fmaf(r, ah0, ai0));
                float hn = fmaf(z, sh[0][k] - n, n);
                sh[0][k] = hn;
                out0[(size_t)t * HH + k] = hn;
            }
            {
                float r = srz[1][k], z = srz[1][64 + k];
                float n = tanhf_(fmaf(r, ah1, ai1));
                float hn = fmaf(z, sh[1][k] - n, n);
                sh[1][k] = hn;
                out1[(size_t)t * HH + k] = hn;
            }
        }
        __syncthreads();
    }
}

// ---------------------------------------------------------------------------
// Layers 1+2 PIPELINED in one CTA (384 threads, one batch).
// Group 0 (warps 0-5) = layer 1 at t = i; group 1 (warps 6-11) = layer 2 at
// t = i-1. Layer 2's x-input is read DIRECTLY from sh1 in phase A (it holds
// h1[i-1]); group 0 overwrites sh1 only in phase B, after the barrier.
// Layer 1's input (layer-0 output) is staged from g_buf via R1's sx ring;
// only layer 2 writes g_buf, trailing the layer-1 reads by 3 steps (in-place
// safe). Sequential steps: 4097 instead of 2*4096.
// ---------------------------------------------------------------------------
__global__ __launch_bounds__(384, 1)
void pipe12_kernel(
    const float* __restrict__ wih1, const float* __restrict__ whh1,
    const float* __restrict__ bih1, const float* __restrict__ bhh1,
    const float* __restrict__ wih2, const float* __restrict__ whh2,
    const float* __restrict__ bih2, const float* __restrict__ bhh2)
{
    __shared__ __align__(16) float sh1[HH];
    __shared__ __align__(16) float sh2[HH];
    __shared__ __align__(16) float sx[2][HH];
    __shared__ float srz[2][128];

    const int tid = threadIdx.x;
    const int g = tid / 192;          // 0 = layer1, 1 = layer2 (warp-uniform)
    const int j = tid % 192;
    const int b = blockIdx.x;
    float* buf = g_buf + (size_t)b * SS * HH;

    const float* wihp = g ? wih2 : wih1;
    const float* whhp = g ? whh2 : whh1;
    float wi[HH], wh[HH];
#pragma unroll
    for (int k = 0; k < HH; k++) {
        wi[k] = wihp[j * HH + k];
        wh[k] = whhp[j * HH + k];
    }
    const float bi = g ? bih2[j] : bih1[j];
    const float bh = g ? bhh2[j] : bhh1[j];

    if (tid < HH) sh1[tid] = 0.0f;
    else if (tid < 2 * HH) sh2[tid - HH] = 0.0f;

    float xreg = 0.0f;
    if (g == 0 && j < HH) {
        sx[0][j] = buf[j];                       // layer-0 out, t = 0
        xreg = buf[(size_t)HH + j];              // t = 1
    }
    __syncthreads();

    for (int i = 0; i <= SS; i++) {
        const bool active = g ? (i >= 1) : (i < SS);
        float ai = 0.f, ah = 0.f;
        if (active) {
            const float* xv = g ? sh1 : sx[i & 1];   // L2 input = h1[i-1]
            ai = dot64_(wi, xv) + bi;
            ah = dot64_(wh, g ? sh2 : sh1) + bh;
            if (j < 128) srz[g][j] = sigmoidf_(ai + ah);
        }
        __syncthreads();
        if (active) {
            if (j >= 128) {
                const int k = j - 128;
                float r = srz[g][k], z = srz[g][64 + k];
                float n = tanhf_(fmaf(r, ah, ai));
                float* shh = g ? sh2 : sh1;
                float hp = shh[k];
                float hn = fmaf(z, hp - n, n);
                shh[k] = hn;
                if (g) buf[(size_t)(i - 1) * HH + k] = hn;   // only L2 writes
            } else if (g == 0 && j < HH) {
                sx[1 - (i & 1)][j] = xreg;
                xreg = (i + 2 < SS) ? buf[(size_t)(i + 2) * HH + j] : 0.0f;
            }
        }
        __syncthreads();
    }
}

// ---------------------------------------------------------------------------
// Attention + head (unchanged; known-good).
// ---------------------------------------------------------------------------
__global__ __launch_bounds__(256)
void attn_kernel(
    const float* __restrict__ in_proj_w, const float* __restrict__ in_proj_b,
    const float* __restrict__ out_proj_w, const float* __restrict__ out_proj_b,
    const float* __restrict__ fc_w, const float* __restrict__ fc_b,
    float* __restrict__ out)
{
    const int b = blockIdx.x;
    const int tid = threadIdx.x;

    __shared__ __align__(16) float shl[HH];
    __shared__ __align__(16) float sq[HH];
    __shared__ __align__(16) float sg[4][HH];
    __shared__ float sc[4];
    __shared__ float sred[4][256];
    __shared__ float sm4[4], sl4[4];
    __shared__ __align__(16) float stile[64][HH];
    __shared__ float sw[4][64];
    __shared__ float su[4][HH];
    __shared__ __align__(16) float sctx[HH];
    __shared__ float sao[HH];

    const float* mybuf = g_buf + (size_t)b * SS * HH;

    if (tid < HH) shl[tid] = mybuf[(size_t)(SS - 1) * HH + tid];
    __syncthreads();

    if (tid < HH) {
        float acc = in_proj_b[tid];
#pragma unroll
        for (int k = 0; k < HH; k++)
            acc = fmaf(in_proj_w[tid * HH + k], shl[k], acc);
        sq[tid] = acc;
    }
    __syncthreads();

    if (tid < HH) {
#pragma unroll
        for (int h = 0; h < 4; h++) {
            float acc = 0.0f;
#pragma unroll
            for (int d = 0; d < 16; d++)
                acc = fmaf(sq[h * 16 + d], in_proj_w[(HH + h * 16 + d) * HH + tid], acc);
            sg[h][tid] = acc * 0.25f;
        }
    }
    if (tid < 4) {
        float acc = 0.0f;
#pragma unroll
        for (int d = 0; d < 16; d++)
            acc = fmaf(sq[tid * 16 + d], in_proj_b[HH + tid * 16 + d], acc);
        sc[tid] = acc * 0.25f;
    }
    __syncthreads();

    float mloc[4] = {-1e30f, -1e30f, -1e30f, -1e30f};
    for (int s = tid; s < SS; s += 256) {
        const float4* ov = (const float4*)(mybuf + (size_t)s * HH);
        float4 o[16];
#pragma unroll
        for (int kk = 0; kk < 16; kk++) o[kk] = ov[kk];
#pragma unroll
        for (int h = 0; h < 4; h++) {
            const float4* gv = (const float4*)sg[h];
            float a0 = sc[h], a1 = 0.f, a2 = 0.f, a3 = 0.f;
#pragma unroll
            for (int kk = 0; kk < 16; kk++) {
                float4 g4 = gv[kk];
                a0 = fmaf(g4.x, o[kk].x, a0);
                a1 = fmaf(g4.y, o[kk].y, a1);
                a2 = fmaf(g4.z, o[kk].z, a2);
                a3 = fmaf(g4.w, o[kk].w, a3);
            }
            float sv = (a0 + a1) + (a2 + a3);
            g_scores[((size_t)(b * 4 + h)) * SS + s] = sv;
            mloc[h] = fmaxf(mloc[h], sv);
        }
    }
#pragma unroll
    for (int h = 0; h < 4; h++) sred[h][tid] = mloc[h];
    __syncthreads();
    if (tid < 4) {
        float m = -1e30f;
        for (int i = 0; i < 256; i++) m = fmaxf(m, sred[tid][i]);
        sm4[tid] = m;
    }
    __syncthreads();

    const int h = tid >> 6;
    const int e = tid & 63;
    const float mh = sm4[h];
    float uacc = 0.0f, lloc = 0.0f;

    for (int tile = 0; tile < SS / 64; tile++) {
        const int s0 = tile * 64;
        {
            float4* st4 = (float4*)stile;
            const float4* gv = (const float4*)(mybuf + (size_t)s0 * HH);
#pragma unroll
            for (int r = 0; r < 4; r++) {
                int idx = tid + r * 256;
                st4[idx] = gv[idx];
            }
        }
        {
            float w = __expf(g_scores[((size_t)(b * 4 + h)) * SS + s0 + e] - mh);
            sw[h][e] = w;
            lloc += w;
        }
        __syncthreads();
#pragma unroll
        for (int sp = 0; sp < 64; sp++)
            uacc = fmaf(sw[h][sp], stile[sp][e], uacc);
        __syncthreads();
    }

    ((float*)sred)[tid] = lloc;
    __syncthreads();
    if (tid < 4) {
        float l = 0.0f;
        for (int i = 0; i < 64; i++) l += ((float*)sred)[tid * 64 + i];
        sl4[tid] = l;
    }
    __syncthreads();

    su[h][e] = uacc / sl4[h];
    __syncthreads();

    if (tid < HH) {
        const int hh = tid >> 4;
        float acc = in_proj_b[128 + tid];
#pragma unroll
        for (int k = 0; k < HH; k++)
            acc = fmaf(in_proj_w[(128 + tid) * HH + k], su[hh][k], acc);
        sctx[tid] = acc;
    }
    __syncthreads();

    if (tid < HH) {
        float acc = out_proj_b[tid];
#pragma unroll
        for (int k = 0; k < HH; k++)
            acc = fmaf(out_proj_w[tid * HH + k], sctx[k], acc);
        sao[tid] = fc_w[tid] * acc;
    }
    __syncthreads();

    if (tid == 0) {
        float lg = fc_b[0];
        for (int i = 0; i < HH; i++) lg += sao[i];
        out[b] = 1.0f / (1.0f + __expf(-lg));
    }
}

// ---------------------------------------------------------------------------
extern "C" void kernel_launch(void* const* d_in, const int* in_sizes, int n_in,
                              void* d_out, int out_size)
{
    const float* x    = (const float*)d_in[0];
    const float* wih0 = (const float*)d_in[1];
    const float* whh0 = (const float*)d_in[2];
    const float* bih0 = (const float*)d_in[3];
    const float* bhh0 = (const float*)d_in[4];
    const float* wih1 = (const float*)d_in[5];
    const float* whh1 = (const float*)d_in[6];
    const float* bih1 = (const float*)d_in[7];
    const float* bhh1 = (const float*)d_in[8];
    const float* wih2 = (const float*)d_in[9];
    const float* whh2 = (const float*)d_in[10];
    const float* bih2 = (const float*)d_in[11];
    const float* bhh2 = (const float*)d_in[12];
    const float* ipw  = (const float*)d_in[13];
    const float* ipb  = (const float*)d_in[14];
    const float* opw  = (const float*)d_in[15];
    const float* opb  = (const float*)d_in[16];
    const float* fcw  = (const float*)d_in[17];
    const float* fcb  = (const float*)d_in[18];

    rec0_kernel<<<BB / 2, GG>>>(x, wih0, whh0, bih0, bhh0);        // #1
    pipe12_kernel<<<BB, 384>>>(wih1, whh1, bih1, bhh1,             // #2 <- profiled
                               wih2, whh2, bih2, bhh2);
    attn_kernel<<<BB, 256>>>(ipw, ipb, opw, opb, fcw, fcb, (float*)d_out);
}

// round 13
// speedup vs baseline: 2.5397x; 1.3621x over previous
#include <cuda_runtime.h>
#include <math.h>

#define BB 256
#define SS 4096
#define HH 64
#define GG 192   // 3*H

// Scratch
__device__ float g_buf[(size_t)BB * SS * HH];      // 268 MB  layer activations
__device__ float g_scores[(size_t)BB * 4 * SS];    // 16 MB

__device__ __forceinline__ float sigmoidf_(float x) {
    return __fdividef(1.0f, 1.0f + __expf(-x));
}
__device__ __forceinline__ float tanhf_(float x) {
    x = fminf(fmaxf(x, -15.0f), 15.0f);
    float e = __expf(2.0f * x);
    return __fdividef(e - 1.0f, e + 1.0f);
}

// 64-dot, 8 accumulators (serial chain 32 cyc instead of 64)
__device__ __forceinline__ float dot64_(const float* __restrict__ w, const float* sv,
                                        float seed) {
    const float4* hv = (const float4*)sv;
    float a0 = seed, a1 = 0.f, a2 = 0.f, a3 = 0.f;
    float a4 = 0.f, a5 = 0.f, a6 = 0.f, a7 = 0.f;
#pragma unroll
    for (int kk = 0; kk < 16; kk += 2) {
        float4 v0 = hv[kk], v1 = hv[kk + 1];
        a0 = fmaf(w[4 * kk + 0], v0.x, a0);
        a1 = fmaf(w[4 * kk + 1], v0.y, a1);
        a2 = fmaf(w[4 * kk + 2], v0.z, a2);
        a3 = fmaf(w[4 * kk + 3], v0.w, a3);
        a4 = fmaf(w[4 * kk + 4], v1.x, a4);
        a5 = fmaf(w[4 * kk + 5], v1.y, a5);
        a6 = fmaf(w[4 * kk + 6], v1.z, a6);
        a7 = fmaf(w[4 * kk + 7], v1.w, a7);
    }
    return ((a0 + a1) + (a2 + a3)) + ((a4 + a5) + (a6 + a7));
}

// ---------------------------------------------------------------------------
// GRU layer (R1-proven structure). One CTA = one batch, 192 threads = one
// gate row each, weights in registers, h in smem, 2 barriers/step.
// FIRST: x is scalar/step -> per-thread broadcast-LDG register ring (no smem).
// else:  input staged into sx by threads j<64 (R1's double-buffer).
// ---------------------------------------------------------------------------
template <bool FIRST>
__device__ void gru_layer(
    const float* __restrict__ wih, const float* __restrict__ whh,
    const float* __restrict__ bih, const float* __restrict__ bhh,
    const float* __restrict__ inp,   // FIRST: x + b*SS (scalar/step); else buf
    float* __restrict__ outp,        // buf (may alias inp; read t+2 < write t)
    float* sh, float (*sx)[HH], float* srz)
{
    const int j = threadIdx.x;
    constexpr int IN = FIRST ? 1 : HH;

    float wi[IN];
    float wh[HH];
#pragma unroll
    for (int k = 0; k < HH; k++) wh[k] = whh[j * HH + k];
#pragma unroll
    for (int k = 0; k < IN; k++) wi[k] = wih[j * IN + k];
    const float bi = bih[j];
    const float bh = bhh[j];

    if (j < HH) sh[j] = 0.0f;

    float xr[4] = {0.f, 0.f, 0.f, 0.f};   // FIRST: broadcast x ring (all threads)
    float xreg = 0.0f;
    if (FIRST) {
#pragma unroll
        for (int i = 0; i < 4; i++) xr[i] = inp[i];
    } else if (j < IN) {
        sx[0][j] = inp[j];                 // t = 0
        xreg     = inp[(size_t)IN + j];    // t = 1
    }
    __syncthreads();

    for (int t = 0; t < SS; t++) {
        const int cur = t & 1;
        // ---- phase A: input dot + hidden dot ----
        float ai;
        if (FIRST) {
            ai = fmaf(wi[0], xr[t & 3], bi);
            const int tp = t + 4;
            if (tp < SS) xr[t & 3] = inp[tp];
        } else {
            ai = dot64_(wi, sx[cur], bi);
        }
        const float ah = dot64_(wh, sh, bh);

        if (j < 128) srz[j] = sigmoidf_(ai + ah);   // r rows [0,64), z rows [64,128)
        __syncthreads();

        // ---- phase B ----
        if (j >= 128) {
            const int k = j - 128;
            float r = srz[k];
            float z = srz[64 + k];
            float n = tanhf_(fmaf(r, ah, ai));      // tanh(xn + r*hn)
            float hp = sh[k];
            float hn = fmaf(z, hp - n, n);          // (1-z)*n + z*h
            sh[k] = hn;
            outp[(size_t)t * HH + k] = hn;
        } else if (!FIRST && j < IN) {
            sx[1 - cur][j] = xreg;                  // stage x_{t+1}
            xreg = (t + 2 < SS) ? inp[(size_t)(t + 2) * IN + j] : 0.0f;
        }
        __syncthreads();
    }
}

__global__ __launch_bounds__(GG)
void gru_kernel(
    const float* __restrict__ x,
    const float* __restrict__ wih0, const float* __restrict__ whh0,
    const float* __restrict__ bih0, const float* __restrict__ bhh0,
    const float* __restrict__ wih1, const float* __restrict__ whh1,
    const float* __restrict__ bih1, const float* __restrict__ bhh1,
    const float* __restrict__ wih2, const float* __restrict__ whh2,
    const float* __restrict__ bih2, const float* __restrict__ bhh2)
{
    __shared__ __align__(16) float sh[HH];
    __shared__ __align__(16) float sx[2][HH];
    __shared__ float srz[128];

    const int b = blockIdx.x;
    float* buf = g_buf + (size_t)b * SS * HH;

    gru_layer<true >(wih0, whh0, bih0, bhh0, x + (size_t)b * SS, buf, sh, sx, srz);
    __syncthreads();
    gru_layer<false>(wih1, whh1, bih1, bhh1, buf, buf, sh, sx, srz);
    __syncthreads();
    gru_layer<false>(wih2, whh2, bih2, bhh2, buf, buf, sh, sx, srz);
}

// ---------------------------------------------------------------------------
// Attention + head (unchanged; known-good).
// ---------------------------------------------------------------------------
__global__ __launch_bounds__(256)
void attn_kernel(
    const float* __restrict__ in_proj_w, const float* __restrict__ in_proj_b,
    const float* __restrict__ out_proj_w, const float* __restrict__ out_proj_b,
    const float* __restrict__ fc_w, const float* __restrict__ fc_b,
    float* __restrict__ out)
{
    const int b = blockIdx.x;
    const int tid = threadIdx.x;

    __shared__ __align__(16) float shl[HH];
    __shared__ __align__(16) float sq[HH];
    __shared__ __align__(16) float sg[4][HH];
    __shared__ float sc[4];
    __shared__ float sred[4][256];
    __shared__ float sm4[4], sl4[4];
    __shared__ __align__(16) float stile[64][HH];
    __shared__ float sw[4][64];
    __shared__ float su[4][HH];
    __shared__ __align__(16) float sctx[HH];
    __shared__ float sao[HH];

    const float* mybuf = g_buf + (size_t)b * SS * HH;

    if (tid < HH) shl[tid] = mybuf[(size_t)(SS - 1) * HH + tid];
    __syncthreads();

    if (tid < HH) {
        float acc = in_proj_b[tid];
#pragma unroll
        for (int k = 0; k < HH; k++)
            acc = fmaf(in_proj_w[tid * HH + k], shl[k], acc);
        sq[tid] = acc;
    }
    __syncthreads();

    if (tid < HH) {
#pragma unroll
        for (int h = 0; h < 4; h++) {
            float acc = 0.0f;
#pragma unroll
            for (int d = 0; d < 16; d++)
                acc = fmaf(sq[h * 16 + d], in_proj_w[(HH + h * 16 + d) * HH + tid], acc);
            sg[h][tid] = acc * 0.25f;
        }
    }
    if (tid < 4) {
        float acc = 0.0f;
#pragma unroll
        for (int d = 0; d < 16; d++)
            acc = fmaf(sq[tid * 16 + d], in_proj_b[HH + tid * 16 + d], acc);
        sc[tid] = acc * 0.25f;
    }
    __syncthreads();

    float mloc[4] = {-1e30f, -1e30f, -1e30f, -1e30f};
    for (int s = tid; s < SS; s += 256) {
        const float4* ov = (const float4*)(mybuf + (size_t)s * HH);
        float4 o[16];
#pragma unroll
        for (int kk = 0; kk < 16; kk++) o[kk] = ov[kk];
#pragma unroll
        for (int h = 0; h < 4; h++) {
            const float4* gv = (const float4*)sg[h];
            float a0 = sc[h], a1 = 0.f, a2 = 0.f, a3 = 0.f;
#pragma unroll
            for (int kk = 0; kk < 16; kk++) {
                float4 g4 = gv[kk];
                a0 = fmaf(g4.x, o[kk].x, a0);
                a1 = fmaf(g4.y, o[kk].y, a1);
                a2 = fmaf(g4.z, o[kk].z, a2);
                a3 = fmaf(g4.w, o[kk].w, a3);
            }
            float sv = (a0 + a1) + (a2 + a3);
            g_scores[((size_t)(b * 4 + h)) * SS + s] = sv;
            mloc[h] = fmaxf(mloc[h], sv);
        }
    }
#pragma unroll
    for (int h = 0; h < 4; h++) sred[h][tid] = mloc[h];
    __syncthreads();
    if (tid < 4) {
        float m = -1e30f;
        for (int i = 0; i < 256; i++) m = fmaxf(m, sred[tid][i]);
        sm4[tid] = m;
    }
    __syncthreads();

    const int h = tid >> 6;
    const int e = tid & 63;
    const float mh = sm4[h];
    float uacc = 0.0f, lloc = 0.0f;

    for (int tile = 0; tile < SS / 64; tile++) {
        const int s0 = tile * 64;
        {
            float4* st4 = (float4*)stile;
            const float4* gv = (const float4*)(mybuf + (size_t)s0 * HH);
#pragma unroll
            for (int r = 0; r < 4; r++) {
                int idx = tid + r * 256;
                st4[idx] = gv[idx];
            }
        }
        {
            float w = __expf(g_scores[((size_t)(b * 4 + h)) * SS + s0 + e] - mh);
            sw[h][e] = w;
            lloc += w;
        }
        __syncthreads();
#pragma unroll
        for (int sp = 0; sp < 64; sp++)
            uacc = fmaf(sw[h][sp], stile[sp][e], uacc);
        __syncthreads();
    }

    ((float*)sred)[tid] = lloc;
    __syncthreads();
    if (tid < 4) {
        float l = 0.0f;
        for (int i = 0; i < 64; i++) l += ((float*)sred)[tid * 64 + i];
        sl4[tid] = l;
    }
    __syncthreads();

    su[h][e] = uacc / sl4[h];
    __syncthreads();

    if (tid < HH) {
        const int hh = tid >> 4;
        float acc = in_proj_b[128 + tid];
#pragma unroll
        for (int k = 0; k < HH; k++)
            acc = fmaf(in_proj_w[(128 + tid) * HH + k], su[hh][k], acc);
        sctx[tid] = acc;
    }
    __syncthreads();

    if (tid < HH) {
        float acc = out_proj_b[tid];
#pragma unroll
        for (int k = 0; k < HH; k++)
            acc = fmaf(out_proj_w[tid * HH + k], sctx[k], acc);
        sao[tid] = fc_w[tid] * acc;
    }
    __syncthreads();

    if (tid == 0) {
        float lg = fc_b[0];
        for (int i = 0; i < HH; i++) lg += sao[i];
        out[b] = 1.0f / (1.0f + __expf(-lg));
    }
}

// ---------------------------------------------------------------------------
extern "C" void kernel_launch(void* const* d_in, const int* in_sizes, int n_in,
                              void* d_out, int out_size)
{
    const float* x    = (const float*)d_in[0];
    const float* wih0 = (const float*)d_in[1];
    const float* whh0 = (const float*)d_in[2];
    const float* bih0 = (const float*)d_in[3];
    const float* bhh0 = (const float*)d_in[4];
    const float* wih1 = (const float*)d_in[5];
    const float* whh1 = (const float*)d_in[6];
    const float* bih1 = (const float*)d_in[7];
    const float* bhh1 = (const float*)d_in[8];
    const float* wih2 = (const float*)d_in[9];
    const float* whh2 = (const float*)d_in[10];
    const float* bih2 = (const float*)d_in[11];
    const float* bhh2 = (const float*)d_in[12];
    const float* ipw  = (const float*)d_in[13];
    const float* ipb  = (const float*)d_in[14];
    const float* opw  = (const float*)d_in[15];
    const float* opb  = (const float*)d_in[16];
    const float* fcw  = (const float*)d_in[17];
    const float* fcb  = (const float*)d_in[18];

    gru_kernel<<<BB, GG>>>(x, wih0, whh0, bih0, bhh0,
                           wih1, whh1, bih1, bhh1,
                           wih2, whh2, bih2, bhh2);
    attn_kernel<<<BB, 256>>>(ipw, ipb, opw, opb, fcw, fcb, (float*)d_out);
}